// round 12
// baseline (speedup 1.0000x reference)
#include <cuda_runtime.h>

#define NROWS 8192
#define DDIM  8192
#define KIN   1024
#define NT    64
#define GRID  (NROWS / 2)

typedef unsigned long long ull;

// ---- packed f32x2 helpers (Blackwell sm_103a) ----
__device__ __forceinline__ ull pack2(float lo, float hi) {
    ull r; asm("mov.b64 %0, {%1, %2};" : "=l"(r) : "f"(lo), "f"(hi)); return r;
}
__device__ __forceinline__ void unpack2(ull v, float& lo, float& hi) {
    asm("mov.b64 {%0, %1}, %2;" : "=f"(lo), "=f"(hi) : "l"(v));
}
__device__ __forceinline__ ull f2add(ull a, ull b) {
    ull r; asm("add.rn.f32x2 %0, %1, %2;" : "=l"(r) : "l"(a), "l"(b)); return r;
}
// a - b == fma(b, -1, a)
__device__ __forceinline__ ull f2sub(ull a, ull b) {
    const ull NEG1 = 0xBF800000BF800000ULL;
    ull r; asm("fma.rn.f32x2 %0, %1, %2, %3;" : "=l"(r) : "l"(b), "l"(NEG1), "l"(a)); return r;
}
__device__ __forceinline__ ull f2mul(ull a, ull b) {
    ull r; asm("mul.rn.f32x2 %0, %1, %2;" : "=l"(r) : "l"(a), "l"(b)); return r;
}

// Storage swizzle: slot(e) = e ^ (((e>>7)&31)<<2)  (perturbs bits 2..6 only)
__device__ __forceinline__ int slot(int e) {
    return e ^ (((e >> 7) & 31) << 2);
}

// Run-leader scatter of 16 sorted (id, uu) pairs; tail (rare) reads global urow.
__device__ __forceinline__ void scatter16(
    float* sm, const int* id, const float* uu, int prev0,
    int t, const int* __restrict__ idx, const float* __restrict__ urow)
{
    int prev = prev0;
#pragma unroll
    for (int p = 0; p < 16; p++) {
        if (id[p] != prev) {
            float val = uu[p];
            int q = p + 1;
            while (q < 16 && id[q] == id[p]) { val += uu[q]; q++; }
            if (q == 16) {
                int j = 16 * t + 16;   // run spills past this thread's keys (rare)
                while (j < KIN && idx[j] == id[p]) { val += urow[j]; j++; }
            }
            sm[slot(id[p])] = val;
        }
        prev = id[p];
    }
}

// Full per-row FWHT over the scattered smem image; writes scaled output.
__device__ __forceinline__ void fwht_row(
    float* sm, float4* smv, int t, float* __restrict__ orow)
{
    // ==== Phase 1: thread owns e in [128t, 128t+128); bits 0..6 in registers ====
    // e-quad c stored at slot-quad 32t + (c ^ (t&31))  -> 32x LDS.128 conflict-free
    {
        ull y[64];
        const int tm = t & 31;
        const int qb = t << 5;
#pragma unroll
        for (int c = 0; c < 32; c++) {
            float4 q = smv[qb + (c ^ tm)];
            y[2 * c]     = pack2(q.x + q.y, q.x - q.y);   // fold bit 0
            y[2 * c + 1] = pack2(q.z + q.w, q.z - q.w);
        }
        // bits 1..6: 6 packed stages over pair-index p = 0..63
#pragma unroll
        for (int m = 32; m >= 1; m >>= 1) {
#pragma unroll
            for (int j = 0; j < 64; j++) {
                if (!(j & m)) {
                    ull a = y[j], b = y[j | m];
                    y[j]     = f2add(a, b);
                    y[j | m] = f2sub(a, b);
                }
            }
        }
        // write back IN-PLACE (thread-exclusive slots, same addresses)
#pragma unroll
        for (int c = 0; c < 32; c++) {
            float a0, a1, b0, b1;
            unpack2(y[2 * c], a0, a1);
            unpack2(y[2 * c + 1], b0, b1);
            smv[qb + (c ^ tm)] = make_float4(a0, a1, b0, b1);
        }
    }
    __syncthreads();   // P2 reads cross-thread

    // ==== Phase 2: bits 7..12; thread handles tau pair (2t, 2t+1), single pass ====
    {
        ull z[64];
        const int t2 = 2 * t;
#pragma unroll
        for (int m = 0; m < 64; m++) {
            float2 v = *reinterpret_cast<const float2*>(
                &sm[128 * m + (t2 ^ ((m & 31) << 2))]);
            z[m] = pack2(v.x, v.y);   // packed lanes = (tau0, tau1)
        }
        // 6 packed stages over m (bits 7..12)
#pragma unroll
        for (int mm = 32; mm >= 1; mm >>= 1) {
#pragma unroll
            for (int j = 0; j < 64; j++) {
                if (!(j & mm)) {
                    ull a = z[j], b = z[j | mm];
                    z[j]      = f2add(a, b);
                    z[j | mm] = f2sub(a, b);
                }
            }
        }
        // scale + store: float2 at orow[128m + 2t]  -> STG.64, coalesced
        const float SCALE = 0.011048543456039806f;  // 1/sqrt(8192)
        const ull SC2 = pack2(SCALE, SCALE);
        float2* orow2 = reinterpret_cast<float2*>(orow);
#pragma unroll
        for (int m = 0; m < 64; m++) {
            float lo, hi;
            unpack2(f2mul(z[m], SC2), lo, hi);
            orow2[64 * m + t] = make_float2(lo, hi);
        }
    }
}

__global__ void __launch_bounds__(NT, 6) fwht_kernel(
    const float* __restrict__ u, const int* __restrict__ idx, float* __restrict__ out)
{
    __shared__ float  sm[DDIM];       // 32 KB scatter/exchange buffer
    __shared__ float4 stage4[256];    // 4 KB staging for row1's u
    float4* smv = reinterpret_cast<float4*>(sm);

    const int  t  = threadIdx.x;      // 0..63
    const long r0 = 2L * blockIdx.x;
    const float* u0 = u + r0 * KIN;
    const float* u1 = u0 + KIN;

    // ---- early global loads: keys + BOTH rows' values (MLP-rich) ----
    int4   iv[4];
    float4 uv0[4], uv1[4];
    {
        const int4*   idx4 = reinterpret_cast<const int4*>(idx);
        const float4* u04  = reinterpret_cast<const float4*>(u0);
        const float4* u14  = reinterpret_cast<const float4*>(u1);
#pragma unroll
        for (int i = 0; i < 4; i++) {
            iv[i]  = idx4[4 * t + i];
            uv0[i] = u04[4 * t + i];
            uv1[i] = u14[4 * t + i];
        }
    }
    const int prev0 = (t == 0) ? -1 : idx[16 * t - 1];
    int id[16];
#pragma unroll
    for (int i = 0; i < 4; i++) {
        id[4*i] = iv[i].x; id[4*i+1] = iv[i].y; id[4*i+2] = iv[i].z; id[4*i+3] = iv[i].w;
    }

    // ---- zero smem (32KB, STS.128, conflict-free), overlaps LDG latency ----
    const float4 z4 = make_float4(0.f, 0.f, 0.f, 0.f);
#pragma unroll
    for (int i = 0; i < DDIM / 4 / NT; i++) smv[t + NT * i] = z4;
    __syncthreads();

    // ---- ROW 0: scatter from registers ----
    {
        float uu[16];
#pragma unroll
        for (int i = 0; i < 4; i++) {
            uu[4*i] = uv0[i].x; uu[4*i+1] = uv0[i].y; uu[4*i+2] = uv0[i].z; uu[4*i+3] = uv0[i].w;
        }
        scatter16(sm, id, uu, prev0, t, idx, u0);
    }
    // ---- park row1's u in smem staging (own slots, conflict-free, no sync req'd) ----
#pragma unroll
    for (int i = 0; i < 4; i++) stage4[64 * i + t] = uv1[i];
    __syncthreads();

    fwht_row(sm, smv, t, out + (long)r0 * DDIM);
    __syncthreads();   // all P2 reads done before re-zero

    // ---- zero smem again for row 1 ----
#pragma unroll
    for (int i = 0; i < DDIM / 4 / NT; i++) smv[t + NT * i] = z4;
    __syncthreads();

    // ---- ROW 1: scatter from staging (LDS, ~30 cyc instead of cold LDG) ----
    {
        float uu[16];
#pragma unroll
        for (int i = 0; i < 4; i++) {
            float4 w = stage4[64 * i + t];
            uu[4*i] = w.x; uu[4*i+1] = w.y; uu[4*i+2] = w.z; uu[4*i+3] = w.w;
        }
        scatter16(sm, id, uu, prev0, t, idx, u1);
    }
    __syncthreads();

    fwht_row(sm, smv, t, out + (long)(r0 + 1) * DDIM);
}

extern "C" void kernel_launch(void* const* d_in, const int* in_sizes, int n_in,
                              void* d_out, int out_size)
{
    const float* u   = (const float*)d_in[0];
    const int*   idx = (const int*)d_in[1];
    float*       out = (float*)d_out;
    fwht_kernel<<<GRID, NT>>>(u, idx, out);
}

// round 13
// speedup vs baseline: 1.1661x; 1.1661x over previous
#include <cuda_runtime.h>
#include <cstdint>

#define NROWS 8192
#define DDIM  8192
#define KIN   1024
#define NT    64

typedef unsigned long long ull;

// ---- packed f32x2 helpers (Blackwell sm_103a) ----
__device__ __forceinline__ ull pack2(float lo, float hi) {
    ull r; asm("mov.b64 %0, {%1, %2};" : "=l"(r) : "f"(lo), "f"(hi)); return r;
}
__device__ __forceinline__ void unpack2(ull v, float& lo, float& hi) {
    asm("mov.b64 {%0, %1}, %2;" : "=f"(lo), "=f"(hi) : "l"(v));
}
__device__ __forceinline__ ull f2add(ull a, ull b) {
    ull r; asm("add.rn.f32x2 %0, %1, %2;" : "=l"(r) : "l"(a), "l"(b)); return r;
}
// a - b == fma(b, -1, a)
__device__ __forceinline__ ull f2sub(ull a, ull b) {
    const ull NEG1 = 0xBF800000BF800000ULL;
    ull r; asm("fma.rn.f32x2 %0, %1, %2, %3;" : "=l"(r) : "l"(b), "l"(NEG1), "l"(a)); return r;
}
__device__ __forceinline__ ull f2mul(ull a, ull b) {
    ull r; asm("mul.rn.f32x2 %0, %1, %2;" : "=l"(r) : "l"(a), "l"(b)); return r;
}

// Storage swizzle: slot(e) = e ^ (((e>>7)&31)<<2)  (perturbs bits 2..6 only)
__device__ __forceinline__ int slot(int e) {
    return e ^ (((e >> 7) & 31) << 2);
}

// Guaranteed-predicated shared store (no BSSY/BSYNC divergence).
__device__ __forceinline__ void sts_pred(uint32_t addr, float v, int pred) {
    asm volatile(
        "{ .reg .pred p; setp.ne.s32 p, %2, 0; @p st.shared.f32 [%0], %1; }"
        :: "r"(addr), "f"(v), "r"(pred) : "memory");
}

__global__ void __launch_bounds__(NT, 6) fwht_kernel(
    const float* __restrict__ u, const int* __restrict__ idx, float* __restrict__ out)
{
    __shared__ float sm[DDIM];   // 32 KB, single in-place buffer
    float4* smv = reinterpret_cast<float4*>(sm);
    uint32_t smbase;
    asm("{ .reg .u64 q; cvta.to.shared.u64 q, %1; cvt.u32.u64 %0, q; }"
        : "=r"(smbase) : "l"(sm));

    const int t   = threadIdx.x;       // 0..63
    const int row = blockIdx.x;
    const float* urow = u + (long)row * KIN;

    // ---- early global loads (16 keys + 16 values + boundary peek) ----
    int4   iv[4];
    float4 uv[4];
    {
        const int4*   idx4 = reinterpret_cast<const int4*>(idx);
        const float4* u4   = reinterpret_cast<const float4*>(urow);
#pragma unroll
        for (int i = 0; i < 4; i++) { iv[i] = idx4[4 * t + i]; uv[i] = u4[4 * t + i]; }
    }
    const int j16 = 16 * t + 16;
    const int prev0  = (t == 0) ? -1 : idx[16 * t - 1];
    const int idnxt  = (j16     < KIN) ? idx[j16]     : -1;
    const int idnxt2 = (j16 + 1 < KIN) ? idx[j16 + 1] : -1;
    const float unxt = (j16     < KIN) ? urow[j16]    : 0.f;

    // ---- zero smem (32KB, STS.128, conflict-free), overlaps LDG latency ----
    const float4 z4 = make_float4(0.f, 0.f, 0.f, 0.f);
#pragma unroll
    for (int i = 0; i < DDIM / 4 / NT; i++) smv[t + NT * i] = z4;
    __syncthreads();

    // ---- scatter, branch-free: backward run-sum scan + predicated leader stores ----
    {
        int   id[16]; float uu[16];
#pragma unroll
        for (int i = 0; i < 4; i++) {
            id[4*i] = iv[i].x; id[4*i+1] = iv[i].y; id[4*i+2] = iv[i].z; id[4*i+3] = iv[i].w;
            uu[4*i] = uv[i].x; uu[4*i+1] = uv[i].y; uu[4*i+2] = uv[i].z; uu[4*i+3] = uv[i].w;
        }
        // boundary continuation: 1-element tail branchless; >=2 elements very rare
        float tail = (idnxt == id[15]) ? unxt : 0.f;
        if (idnxt == id[15] && idnxt2 == id[15]) {
            int j = j16 + 1;
            while (j < KIN && idx[j] == id[15]) { tail += urow[j]; j++; }
        }
        float s[16];
        s[15] = uu[15] + tail;
#pragma unroll
        for (int p = 14; p >= 0; p--)
            s[p] = uu[p] + ((id[p + 1] == id[p]) ? s[p + 1] : 0.f);
        // predicated leader stores (no branches)
        int pv = prev0;
#pragma unroll
        for (int p = 0; p < 16; p++) {
            sts_pred(smbase + 4u * (uint32_t)slot(id[p]), s[p], id[p] != pv);
            pv = id[p];
        }
    }
    __syncthreads();

    // ==== Phase 1: thread owns e in [128t, 128t+128); bits 0..6 in registers ====
    // e-quad c stored at slot-quad 32t + (c ^ (t&31))  -> 32x LDS.128 conflict-free
    {
        ull y[64];
        const int tm = t & 31;
        const int qb = t << 5;
#pragma unroll
        for (int c = 0; c < 32; c++) {
            float4 q = smv[qb + (c ^ tm)];
            y[2 * c]     = pack2(q.x + q.y, q.x - q.y);   // fold bit 0
            y[2 * c + 1] = pack2(q.z + q.w, q.z - q.w);
        }
        // bits 1..6: 6 packed stages over pair-index p = 0..63
#pragma unroll
        for (int m = 32; m >= 1; m >>= 1) {
#pragma unroll
            for (int j = 0; j < 64; j++) {
                if (!(j & m)) {
                    ull a = y[j], b = y[j | m];
                    y[j]     = f2add(a, b);
                    y[j | m] = f2sub(a, b);
                }
            }
        }
        // write back IN-PLACE (thread-exclusive slots, same addresses)
#pragma unroll
        for (int c = 0; c < 32; c++) {
            float a0, a1, b0, b1;
            unpack2(y[2 * c], a0, a1);
            unpack2(y[2 * c + 1], b0, b1);
            smv[qb + (c ^ tm)] = make_float4(a0, a1, b0, b1);
        }
    }
    __syncthreads();   // P2 reads cross-thread

    // ==== Phase 2: bits 7..12; thread handles tau pair (2t, 2t+1), single pass ====
    // read e = tau + 128m at slot = 128m + (tau ^ ((m&31)<<2)); tau pair adjacent -> LDS.64
    {
        ull z[64];
        const int t2 = 2 * t;
#pragma unroll
        for (int m = 0; m < 64; m++) {
            float2 v = *reinterpret_cast<const float2*>(
                &sm[128 * m + (t2 ^ ((m & 31) << 2))]);
            z[m] = pack2(v.x, v.y);   // packed lanes = (tau0, tau1)
        }
        // 6 packed stages over m (bits 7..12)
#pragma unroll
        for (int mm = 32; mm >= 1; mm >>= 1) {
#pragma unroll
            for (int j = 0; j < 64; j++) {
                if (!(j & mm)) {
                    ull a = z[j], b = z[j | mm];
                    z[j]      = f2add(a, b);
                    z[j | mm] = f2sub(a, b);
                }
            }
        }
        // scale + store: float2 at orow[128m + 2t]  -> STG.64, coalesced
        const float SCALE = 0.011048543456039806f;  // 1/sqrt(8192)
        const ull SC2 = pack2(SCALE, SCALE);
        float2* orow2 = reinterpret_cast<float2*>(out + (long)row * DDIM);
#pragma unroll
        for (int m = 0; m < 64; m++) {
            float lo, hi;
            unpack2(f2mul(z[m], SC2), lo, hi);
            orow2[64 * m + t] = make_float2(lo, hi);
        }
    }
}

extern "C" void kernel_launch(void* const* d_in, const int* in_sizes, int n_in,
                              void* d_out, int out_size)
{
    const float* u   = (const float*)d_in[0];
    const int*   idx = (const int*)d_in[1];
    float*       out = (float*)d_out;
    fwht_kernel<<<NROWS, NT>>>(u, idx, out);
}